// round 1
// baseline (speedup 1.0000x reference)
#include <cuda_runtime.h>
#include <cstdint>

// Problem constants
#define B_    256
#define T_    128
#define NIN   1156
#define NHID  1024
#define NOUT  10
#define M_    (T_ * B_)        // 32768 GEMM rows
#define BETA  0.95f
#define THR   1.0f

// Scratch (static __device__ arrays: no runtime allocation)
__device__ float    g_cur[(size_t)M_ * NHID];          // [T, B, H]  128 MiB
__device__ unsigned g_spk[(size_t)M_ * NHID / 32];     // packed spikes, 4 MiB
__device__ float    g_y  [(size_t)M_ * NOUT];          // [T, B, 10] 1.25 MiB

// ---------------------------------------------------------------------------
// Kernel 1: CUR[m, h] = sum_k X[b, t, k] * W1[h, k],  m = t*B_ + b
// 128x128 tile, BK=8, 8x8 microtile, 256 threads.
// ---------------------------------------------------------------------------
#define BM 128
#define BN 128
#define BK 8
#define TM 8
#define TN 8

__global__ __launch_bounds__(256)
void gemm1_kernel(const float* __restrict__ x, const float* __restrict__ W1)
{
    __shared__ float As[BK][BM];
    __shared__ float Bs[BK][BN];

    const int tid  = threadIdx.x;
    const int brow = blockIdx.y;   // M tile: 0..255
    const int bcol = blockIdx.x;   // N tile: 0..7

    // Global-load mapping: each thread loads one float4 of A and one of B.
    const int ld_r = tid >> 1;           // 0..127
    const int ld_c = (tid & 1) * 4;      // 0 or 4

    // A row m -> x offset: t = m / B_, b = m % B_, x[(b*T_ + t)*NIN]
    const int m_ld = brow * BM + ld_r;
    const int t_ld = m_ld >> 8;          // / 256
    const int b_ld = m_ld & 255;
    const float* a_ptr = x + ((size_t)b_ld * T_ + t_ld) * NIN + ld_c;

    const int h_ld = bcol * BN + ld_r;
    const float* b_ptr = W1 + (size_t)h_ld * NIN + ld_c;

    const int tx = tid & 15;   // 0..15 -> N
    const int ty = tid >> 4;   // 0..15 -> M

    float acc[TM][TN];
#pragma unroll
    for (int i = 0; i < TM; i++)
#pragma unroll
        for (int j = 0; j < TN; j++) acc[i][j] = 0.f;

    for (int k0 = 0; k0 < NIN; k0 += BK) {
        // K tail: NIN % 4 == 0, so each float4 chunk is fully valid or fully OOB
        float4 av = make_float4(0.f, 0.f, 0.f, 0.f);
        float4 bv = make_float4(0.f, 0.f, 0.f, 0.f);
        if (k0 + ld_c < NIN) {
            av = *reinterpret_cast<const float4*>(a_ptr + k0);
            bv = *reinterpret_cast<const float4*>(b_ptr + k0);
        }
        As[ld_c + 0][ld_r] = av.x;
        As[ld_c + 1][ld_r] = av.y;
        As[ld_c + 2][ld_r] = av.z;
        As[ld_c + 3][ld_r] = av.w;
        Bs[ld_c + 0][ld_r] = bv.x;
        Bs[ld_c + 1][ld_r] = bv.y;
        Bs[ld_c + 2][ld_r] = bv.z;
        Bs[ld_c + 3][ld_r] = bv.w;
        __syncthreads();

#pragma unroll
        for (int kk = 0; kk < BK; kk++) {
            float ar[TM], br[TN];
            *reinterpret_cast<float4*>(&ar[0]) =
                *reinterpret_cast<const float4*>(&As[kk][ty * TM]);
            *reinterpret_cast<float4*>(&ar[4]) =
                *reinterpret_cast<const float4*>(&As[kk][ty * TM + 4]);
            *reinterpret_cast<float4*>(&br[0]) =
                *reinterpret_cast<const float4*>(&Bs[kk][tx * TN]);
            *reinterpret_cast<float4*>(&br[4]) =
                *reinterpret_cast<const float4*>(&Bs[kk][tx * TN + 4]);
#pragma unroll
            for (int i = 0; i < TM; i++)
#pragma unroll
                for (int j = 0; j < TN; j++)
                    acc[i][j] += ar[i] * br[j];
        }
        __syncthreads();
    }

    // Store CUR[m * NHID + h], vectorized
#pragma unroll
    for (int i = 0; i < TM; i++) {
        const size_t row = (size_t)(brow * BM + ty * TM + i) * NHID
                         + bcol * BN + tx * TN;
        *reinterpret_cast<float4*>(&g_cur[row]) =
            make_float4(acc[i][0], acc[i][1], acc[i][2], acc[i][3]);
        *reinterpret_cast<float4*>(&g_cur[row + 4]) =
            make_float4(acc[i][4], acc[i][5], acc[i][6], acc[i][7]);
    }
}

// ---------------------------------------------------------------------------
// Kernel 2: per-(b,h) LIF scan over t; emit packed spike bits via ballot.
// ---------------------------------------------------------------------------
__global__ __launch_bounds__(256)
void spike_scan_kernel()
{
    const int tid = blockIdx.x * blockDim.x + threadIdx.x;  // 0..262143 = b*NHID+h
    const int BH  = B_ * NHID;
    const int widx = tid >> 5;
    float mem1 = 0.f;

    for (int t = 0; t < T_; t++) {
        const float c = g_cur[(size_t)t * BH + tid];
        const float reset = (mem1 > THR) ? THR : 0.f;
        mem1 = BETA * mem1 + c - reset;
        const unsigned bal = __ballot_sync(0xffffffffu, (mem1 - THR) > 0.f);
        if ((tid & 31) == 0)
            g_spk[(size_t)t * (BH / 32) + widx] = bal;
    }
}

// ---------------------------------------------------------------------------
// Kernel 3: Y[t, b, o] = sum_h spk[t,b,h] * W2[o, h]   (bit-sparse dot)
// One thread per (t,b) row; W2 (40 KB) staged in smem.
// ---------------------------------------------------------------------------
__global__ __launch_bounds__(256)
void ygemm_kernel(const float* __restrict__ W2)
{
    __shared__ float w2s[NOUT * NHID];
    for (int i = threadIdx.x; i < NOUT * NHID; i += blockDim.x)
        w2s[i] = W2[i];
    __syncthreads();

    const int row = blockIdx.x * blockDim.x + threadIdx.x;  // 0..32767 = t*B_ + b
    float acc[NOUT];
#pragma unroll
    for (int o = 0; o < NOUT; o++) acc[o] = 0.f;

    const unsigned* sp = g_spk + (size_t)row * (NHID / 32);
#pragma unroll 4
    for (int w = 0; w < NHID / 32; w++) {
        unsigned bits = sp[w];
        while (bits) {
            const int j = __ffs(bits) - 1;
            bits &= bits - 1;
            const int h = (w << 5) + j;
#pragma unroll
            for (int o = 0; o < NOUT; o++)
                acc[o] += w2s[o * NHID + h];
        }
    }

    float* yp = g_y + (size_t)row * NOUT;
#pragma unroll
    for (int o = 0; o < NOUT; o++) yp[o] = acc[o];
}

// ---------------------------------------------------------------------------
// Kernel 4: mem2 leaky scan over t, write output [T, B, NOUT]
// ---------------------------------------------------------------------------
__global__ __launch_bounds__(256)
void out_scan_kernel(float* __restrict__ out)
{
    const int idx = blockIdx.x * blockDim.x + threadIdx.x;  // 0..2559 = b*10+o
    if (idx >= B_ * NOUT) return;
    float mem2 = 0.f;
#pragma unroll 4
    for (int t = 0; t < T_; t++) {
        mem2 = BETA * mem2 + g_y[(size_t)t * (B_ * NOUT) + idx];
        out[(size_t)t * (B_ * NOUT) + idx] = mem2;
    }
}

// ---------------------------------------------------------------------------
extern "C" void kernel_launch(void* const* d_in, const int* in_sizes, int n_in,
                              void* d_out, int out_size)
{
    const float* x  = (const float*)d_in[0];   // [B, T, NIN]
    const float* W1 = (const float*)d_in[1];   // [NHID, NIN]
    const float* W2 = (const float*)d_in[2];   // [NOUT, NHID]
    float* out = (float*)d_out;                // [T, B, NOUT]

    dim3 grid1(NHID / BN, M_ / BM);            // (8, 256)
    gemm1_kernel<<<grid1, 256>>>(x, W1);

    spike_scan_kernel<<<(B_ * NHID) / 256, 256>>>();

    ygemm_kernel<<<M_ / 256, 256>>>(W2);

    out_scan_kernel<<<(B_ * NOUT + 255) / 256, 256>>>(out);
}

// round 7
// speedup vs baseline: 1.2973x; 1.2973x over previous
#include <cuda_runtime.h>
#include <cstdint>

// Problem constants
#define B_    256
#define T_    128
#define NIN   1156
#define NHID  1024
#define NOUT  10
#define M_    (T_ * B_)
#define BETA  0.95f
#define THR   1.0f

// Scratch
__device__ float    g_cur[(size_t)M_ * NHID];          // [T, B, H]  128 MiB
__device__ unsigned g_spk[(size_t)M_ * NHID / 32];     // packed spikes
__device__ float    g_y  [(size_t)M_ * NOUT];

// ---------------------------------------------------------------------------
// GEMM1: CUR[m,h] = sum_k X[b,t,k] * W1[h,k], m = t*256+b
// TF32 hi/lo split (hh+hl+lh) via mma.sync.m16n8k8.tf32, with CHUNK-LOCAL
// mma accumulators drained into persistent fp32 registers via RN adds
// (defeats biased truncation in the tensor-core accumulate chain).
// CTA 128x128, k-chunk 32, double-buffered smem, register prefetch.
// ---------------------------------------------------------------------------
#define KCH     37                 // ceil(1156/32)
#define S_F     36                 // floats per smem row (32 data + 4 pad)
#define TILE_F  (128 * S_F)        // 4608 floats
#define OFF_AHI 0
#define OFF_ALO (TILE_F)
#define OFF_BHI (2 * TILE_F)
#define OFF_BLO (3 * TILE_F)
#define STAGE_F (4 * TILE_F)       // 18432 floats
#define SMEM_DYN (2 * STAGE_F * 4) // 147456 bytes

// tf32 round: destination is a .b32 register in PTX
__device__ __forceinline__ uint32_t tf32r(float x) {
    uint32_t r;
    asm("cvt.rna.tf32.f32 %0, %1;" : "=r"(r) : "f"(x));
    return r;
}

__device__ __forceinline__ void mma_tf32(float* c, const uint32_t* a, const uint32_t* b) {
    asm volatile(
        "mma.sync.aligned.m16n8k8.row.col.f32.tf32.tf32.f32 "
        "{%0,%1,%2,%3}, {%4,%5,%6,%7}, {%8,%9}, {%0,%1,%2,%3};"
        : "+f"(c[0]), "+f"(c[1]), "+f"(c[2]), "+f"(c[3])
        : "r"(a[0]), "r"(a[1]), "r"(a[2]), "r"(a[3]), "r"(b[0]), "r"(b[1]));
}

__device__ __forceinline__ uint32_t f2u(float v) { return __float_as_uint(v); }

__global__ __launch_bounds__(256)
void gemm1_tf32_kernel(const float* __restrict__ x, const float* __restrict__ W1)
{
    extern __shared__ float sm[];

    const int tid   = threadIdx.x;
    const int lane  = tid & 31;
    const int w     = tid >> 5;
    const int mtile = blockIdx.y;     // 0..255
    const int ntile = blockIdx.x;     // 0..7
    const int MW    = (w & 1) * 64;   // warp m offset in CTA tile
    const int NW    = (w >> 1) * 32;  // warp n offset
    const int qa    = lane >> 2;      // 0..7
    const int pa    = lane & 3;       // 0..3

    // --- global load plan: 4 float4 each for A and B per chunk ---
    const float* aptr[4];
    const float* bptr[4];
    int rowL[4], c4L[4];
#pragma unroll
    for (int i = 0; i < 4; i++) {
        const int idx = tid + i * 256;       // 0..1023
        const int row = idx >> 3;            // 0..127
        const int c4  = idx & 7;             // 0..7
        rowL[i] = row; c4L[i] = c4;
        const int m = mtile * 128 + row;
        const int t = m >> 8;
        const int b = m & 255;
        aptr[i] = x + ((size_t)b * T_ + t) * NIN + c4 * 4;
        bptr[i] = W1 + (size_t)(ntile * 128 + row) * NIN + c4 * 4;
    }

    float acc[4][4][4];   // persistent accumulators (RN adds only)
#pragma unroll
    for (int mi = 0; mi < 4; mi++)
#pragma unroll
        for (int nj = 0; nj < 4; nj++)
#pragma unroll
            for (int q = 0; q < 4; q++) acc[mi][nj][q] = 0.f;

    float4 av[4], bv[4];

    // producer: split one float4 into tf32 hi/lo and store
    auto store_split = [&](float* base_hi, float* base_lo, int i, float4 v) {
        float4 hi, lo;
        hi.x = __uint_as_float(tf32r(v.x)); lo.x = __uint_as_float(tf32r(v.x - hi.x));
        hi.y = __uint_as_float(tf32r(v.y)); lo.y = __uint_as_float(tf32r(v.y - hi.y));
        hi.z = __uint_as_float(tf32r(v.z)); lo.z = __uint_as_float(tf32r(v.z - hi.z));
        hi.w = __uint_as_float(tf32r(v.w)); lo.w = __uint_as_float(tf32r(v.w - hi.w));
        const int off = rowL[i] * S_F + c4L[i] * 4;
        *reinterpret_cast<float4*>(base_hi + off) = hi;
        *reinterpret_cast<float4*>(base_lo + off) = lo;
    };

    // ---- prologue: load + split chunk 0 into stage 0 ----
    {
#pragma unroll
        for (int i = 0; i < 4; i++) {
            av[i] = *reinterpret_cast<const float4*>(aptr[i]);
            bv[i] = *reinterpret_cast<const float4*>(bptr[i]);
        }
#pragma unroll
        for (int i = 0; i < 4; i++) {
            store_split(sm + OFF_AHI, sm + OFF_ALO, i, av[i]);
            store_split(sm + OFF_BHI, sm + OFF_BLO, i, bv[i]);
        }
        __syncthreads();
    }

    for (int c = 0; c < KCH; c++) {
        // prefetch chunk c+1 into registers
        if (c + 1 < KCH) {
            const int k0 = (c + 1) * 32;
#pragma unroll
            for (int i = 0; i < 4; i++) {
                if (k0 + c4L[i] * 4 < NIN) {
                    av[i] = *reinterpret_cast<const float4*>(aptr[i] + k0);
                    bv[i] = *reinterpret_cast<const float4*>(bptr[i] + k0);
                } else {
                    av[i] = make_float4(0.f, 0.f, 0.f, 0.f);
                    bv[i] = make_float4(0.f, 0.f, 0.f, 0.f);
                }
            }
        }

        // compute on stage c&1; two mi-halves with chunk-local accumulators
        const float* st = sm + (c & 1) * STAGE_F;
#pragma unroll
        for (int mh = 0; mh < 2; mh++) {
            float accT[2][4][4];
#pragma unroll
            for (int mi = 0; mi < 2; mi++)
#pragma unroll
                for (int nj = 0; nj < 4; nj++)
#pragma unroll
                    for (int q = 0; q < 4; q++) accT[mi][nj][q] = 0.f;

#pragma unroll
            for (int ks = 0; ks < 4; ks++) {
                uint32_t ah[2][4], al[2][4], bh[4][2], bl[4][2];
                const int kc = ks * 8 + pa;
#pragma unroll
                for (int mt = 0; mt < 2; mt++) {
                    const int r0 = (MW + (mh * 2 + mt) * 16 + qa) * S_F + kc;
                    const float* pH = st + OFF_AHI + r0;
                    const float* pL = st + OFF_ALO + r0;
                    ah[mt][0] = f2u(pH[0]);
                    ah[mt][1] = f2u(pH[8 * S_F]);
                    ah[mt][2] = f2u(pH[4]);
                    ah[mt][3] = f2u(pH[8 * S_F + 4]);
                    al[mt][0] = f2u(pL[0]);
                    al[mt][1] = f2u(pL[8 * S_F]);
                    al[mt][2] = f2u(pL[4]);
                    al[mt][3] = f2u(pL[8 * S_F + 4]);
                }
#pragma unroll
                for (int nt = 0; nt < 4; nt++) {
                    const int r0 = (NW + nt * 8 + qa) * S_F + kc;
                    const float* pH = st + OFF_BHI + r0;
                    const float* pL = st + OFF_BLO + r0;
                    bh[nt][0] = f2u(pH[0]);
                    bh[nt][1] = f2u(pH[4]);
                    bl[nt][0] = f2u(pL[0]);
                    bl[nt][1] = f2u(pL[4]);
                }
#pragma unroll
                for (int mi = 0; mi < 2; mi++)
#pragma unroll
                    for (int nj = 0; nj < 4; nj++) {
                        mma_tf32(accT[mi][nj], ah[mi], bh[nj]);
                        mma_tf32(accT[mi][nj], ah[mi], bl[nj]);
                        mma_tf32(accT[mi][nj], al[mi], bh[nj]);
                    }
            }

            // RN drain into persistent accumulators
#pragma unroll
            for (int mi = 0; mi < 2; mi++)
#pragma unroll
                for (int nj = 0; nj < 4; nj++)
#pragma unroll
                    for (int q = 0; q < 4; q++)
                        acc[mh * 2 + mi][nj][q] += accT[mi][nj][q];
        }

        // store prefetched chunk into the other stage
        if (c + 1 < KCH) {
            float* dst = sm + ((c + 1) & 1) * STAGE_F;
#pragma unroll
            for (int i = 0; i < 4; i++) {
                store_split(dst + OFF_AHI, dst + OFF_ALO, i, av[i]);
                store_split(dst + OFF_BHI, dst + OFF_BLO, i, bv[i]);
            }
            __syncthreads();
        }
    }

    // ---- epilogue ----
    const int mbase = mtile * 128 + MW + (lane >> 2);
    const int nbase = ntile * 128 + NW + (lane & 3) * 2;
#pragma unroll
    for (int mi = 0; mi < 4; mi++)
#pragma unroll
        for (int nj = 0; nj < 4; nj++) {
            const int r = mbase + mi * 16;
            const int col = nbase + nj * 8;
            *reinterpret_cast<float2*>(&g_cur[(size_t)r * NHID + col]) =
                make_float2(acc[mi][nj][0], acc[mi][nj][1]);
            *reinterpret_cast<float2*>(&g_cur[(size_t)(r + 8) * NHID + col]) =
                make_float2(acc[mi][nj][2], acc[mi][nj][3]);
        }
}

// ---------------------------------------------------------------------------
// Kernel 2: per-(b,h) LIF scan; packed spike bits via ballot.
// ---------------------------------------------------------------------------
__global__ __launch_bounds__(256)
void spike_scan_kernel()
{
    const int tid  = blockIdx.x * blockDim.x + threadIdx.x;
    const int BH   = B_ * NHID;
    const int widx = tid >> 5;
    float mem1 = 0.f;

    for (int t = 0; t < T_; t++) {
        const float c = g_cur[(size_t)t * BH + tid];
        const float reset = (mem1 > THR) ? THR : 0.f;
        mem1 = BETA * mem1 + c - reset;
        const unsigned bal = __ballot_sync(0xffffffffu, (mem1 - THR) > 0.f);
        if ((tid & 31) == 0)
            g_spk[(size_t)t * (BH / 32) + widx] = bal;
    }
}

// ---------------------------------------------------------------------------
// Kernel 3: Y[t,b,o] = sum_h spk[t,b,h] * W2[o,h]
// ---------------------------------------------------------------------------
__global__ __launch_bounds__(256)
void ygemm_kernel(const float* __restrict__ W2)
{
    __shared__ float w2s[NOUT * NHID];
    for (int i = threadIdx.x; i < NOUT * NHID; i += blockDim.x)
        w2s[i] = W2[i];
    __syncthreads();

    const int row = blockIdx.x * blockDim.x + threadIdx.x;
    float acc[NOUT];
#pragma unroll
    for (int o = 0; o < NOUT; o++) acc[o] = 0.f;

    const unsigned* sp = g_spk + (size_t)row * (NHID / 32);
#pragma unroll 4
    for (int wd = 0; wd < NHID / 32; wd++) {
        unsigned bits = sp[wd];
        while (bits) {
            const int j = __ffs(bits) - 1;
            bits &= bits - 1;
            const int h = (wd << 5) + j;
#pragma unroll
            for (int o = 0; o < NOUT; o++)
                acc[o] += w2s[o * NHID + h];
        }
    }

    float* yp = g_y + (size_t)row * NOUT;
#pragma unroll
    for (int o = 0; o < NOUT; o++) yp[o] = acc[o];
}

// ---------------------------------------------------------------------------
// Kernel 4: mem2 leaky scan, write output [T, B, NOUT]
// ---------------------------------------------------------------------------
__global__ __launch_bounds__(256)
void out_scan_kernel(float* __restrict__ out)
{
    const int idx = blockIdx.x * blockDim.x + threadIdx.x;
    if (idx >= B_ * NOUT) return;
    float mem2 = 0.f;
#pragma unroll 4
    for (int t = 0; t < T_; t++) {
        mem2 = BETA * mem2 + g_y[(size_t)t * (B_ * NOUT) + idx];
        out[(size_t)t * (B_ * NOUT) + idx] = mem2;
    }
}

// ---------------------------------------------------------------------------
extern "C" void kernel_launch(void* const* d_in, const int* in_sizes, int n_in,
                              void* d_out, int out_size)
{
    const float* x  = (const float*)d_in[0];   // [B, T, NIN]
    const float* W1 = (const float*)d_in[1];   // [NHID, NIN]
    const float* W2 = (const float*)d_in[2];   // [NOUT, NHID]
    float* out = (float*)d_out;                // [T, B, NOUT]

    cudaFuncSetAttribute(gemm1_tf32_kernel,
                         cudaFuncAttributeMaxDynamicSharedMemorySize, SMEM_DYN);

    dim3 grid1(NHID / 128, M_ / 128);          // (8, 256)
    gemm1_tf32_kernel<<<grid1, 256, SMEM_DYN>>>(x, W1);

    spike_scan_kernel<<<(B_ * NHID) / 256, 256>>>();

    ygemm_kernel<<<M_ / 256, 256>>>(W2);

    out_scan_kernel<<<(B_ * NOUT + 255) / 256, 256>>>(out);
}

// round 9
// speedup vs baseline: 2.0823x; 1.6051x over previous
#include <cuda_runtime.h>
#include <cuda_fp16.h>
#include <cstdint>

// Problem constants
#define B_    256
#define T_    128
#define NIN   1156
#define NHID  1024
#define NOUT  10
#define M_    (T_ * B_)
#define BETA  0.95f
#define THR   1.0f

// Scratch
__device__ float    g_cur[(size_t)M_ * NHID];          // [T, B, H]  128 MiB
__device__ unsigned g_spk[(size_t)M_ * NHID / 32];     // packed spikes
__device__ float    g_y  [(size_t)M_ * NOUT];

// ---------------------------------------------------------------------------
// GEMM1: CUR[m,h] = sum_k X[b,t,k] * W1[h,k], m = t*256+b
// Scaled fp16 split: a = a_hi + a_lo/2048,  w*1024 = w_hi + w_lo/2048
// (all components in fp16 NORMAL range -> no denormal flush).
// cur1 = (SUM_hh + SUM_c / 2048) / 1024,  c = a_hi*w_lo + a_lo*w_hi.
// Chunk-local mma accumulators drained with RN adds (kills truncation bias).
// mma.sync.m16n8k16.f16, ldmatrix fragments, CTA 128x128, k-chunk 32,
// double-buffered smem, register prefetch.
// ---------------------------------------------------------------------------
#define KCH      37                // ceil(1156/32)
#define ROWB     80                // bytes per smem row (32 fp16 + 8 pad)
#define TILE_SB  (128 * ROWB)      // 10240 B
#define OFF_AHI  0
#define OFF_ALO  (TILE_SB)
#define OFF_BHI  (2 * TILE_SB)
#define OFF_BLO  (3 * TILE_SB)
#define STAGE_SB (4 * TILE_SB)     // 40960 B
#define SMEM_DYN (2 * STAGE_SB)    // 81920 B

__device__ __forceinline__ void ldm_x4(uint32_t addr, uint32_t& r0, uint32_t& r1,
                                       uint32_t& r2, uint32_t& r3) {
    asm volatile("ldmatrix.sync.aligned.m8n8.x4.shared.b16 {%0,%1,%2,%3}, [%4];"
                 : "=r"(r0), "=r"(r1), "=r"(r2), "=r"(r3) : "r"(addr));
}

__device__ __forceinline__ void mma_f16(float* c, const uint32_t* a, const uint32_t* b) {
    asm volatile(
        "mma.sync.aligned.m16n8k16.row.col.f32.f16.f16.f32 "
        "{%0,%1,%2,%3}, {%4,%5,%6,%7}, {%8,%9}, {%0,%1,%2,%3};"
        : "+f"(c[0]), "+f"(c[1]), "+f"(c[2]), "+f"(c[3])
        : "r"(a[0]), "r"(a[1]), "r"(a[2]), "r"(a[3]), "r"(b[0]), "r"(b[1]));
}

// scaled fp16 hi/lo split of two pre-scaled floats:
// v = hi + lo/2048, hi = fp16(v), lo = fp16((v-hi)*2048)   (lo in normal range)
__device__ __forceinline__ void split_pack(float v0, float v1,
                                           uint32_t& hi, uint32_t& lo) {
    __half h0 = __float2half_rn(v0);
    __half h1 = __float2half_rn(v1);
    __half l0 = __float2half_rn((v0 - __half2float(h0)) * 2048.f);
    __half l1 = __float2half_rn((v1 - __half2float(h1)) * 2048.f);
    __half2 hp = __halves2half2(h0, h1);
    __half2 lp = __halves2half2(l0, l1);
    hi = *reinterpret_cast<uint32_t*>(&hp);
    lo = *reinterpret_cast<uint32_t*>(&lp);
}

__global__ __launch_bounds__(256, 1)
void gemm1_mma_kernel(const float* __restrict__ x, const float* __restrict__ W1)
{
    extern __shared__ char smem[];
    uint32_t sbase;
    asm("{ .reg .u64 t; cvta.to.shared.u64 t, %1; cvt.u32.u64 %0, t; }"
        : "=r"(sbase) : "l"(smem));

    const int tid   = threadIdx.x;
    const int lane  = tid & 31;
    const int w     = tid >> 5;
    const int mtile = blockIdx.y;     // 0..255
    const int ntile = blockIdx.x;     // 0..7
    const int MW    = (w & 1) * 64;   // warp m offset
    const int NW    = (w >> 1) * 32;  // warp n offset

    // --- global load plan: 4 float4 each for A and B per chunk ---
    const float* aptr[4];
    const float* bptr[4];
    int rowL[4], c4L[4];
#pragma unroll
    for (int i = 0; i < 4; i++) {
        const int idx = tid + i * 256;       // 0..1023
        const int row = idx >> 3;            // 0..127
        const int c4  = idx & 7;             // 0..7
        rowL[i] = row; c4L[i] = c4;
        const int m = mtile * 128 + row;
        const int t = m >> 8;
        const int b = m & 255;
        aptr[i] = x + ((size_t)b * T_ + t) * NIN + c4 * 4;
        bptr[i] = W1 + (size_t)(ntile * 128 + row) * NIN + c4 * 4;
    }

    float acc[4][4][4];   // persistent accumulators (RN adds only)
#pragma unroll
    for (int mi = 0; mi < 4; mi++)
#pragma unroll
        for (int nj = 0; nj < 4; nj++)
#pragma unroll
            for (int q = 0; q < 4; q++) acc[mi][nj][q] = 0.f;

    // ldmatrix lane addressing (byte offsets within a stage)
    const int sub = lane >> 3;
    const int l7  = lane & 7;
    const int a_r = MW + (sub & 1) * 8 + l7;
    const int a_c = (sub >> 1) * 8;          // f16 col offset (+ks*16)
    const int b_r = NW + (sub >> 1) * 8 + l7;
    const int b_c = (sub & 1) * 8;

    float4 av[4], bv[4];

    // producer: split A (unscaled) and B (x1024) into fp16 hi/lo and store
    auto store_stage = [&](char* dst) {
#pragma unroll
        for (int i = 0; i < 4; i++) {
            const uint32_t off = (uint32_t)(rowL[i] * ROWB + c4L[i] * 8);
            uint2 hi, lo;
            split_pack(av[i].x, av[i].y, hi.x, lo.x);
            split_pack(av[i].z, av[i].w, hi.y, lo.y);
            *reinterpret_cast<uint2*>(dst + (OFF_AHI + off)) = hi;
            *reinterpret_cast<uint2*>(dst + (OFF_ALO + off)) = lo;
            split_pack(bv[i].x * 1024.f, bv[i].y * 1024.f, hi.x, lo.x);
            split_pack(bv[i].z * 1024.f, bv[i].w * 1024.f, hi.y, lo.y);
            *reinterpret_cast<uint2*>(dst + (OFF_BHI + off)) = hi;
            *reinterpret_cast<uint2*>(dst + (OFF_BLO + off)) = lo;
        }
    };

    // ---- prologue: load + split chunk 0 into stage 0 ----
    {
#pragma unroll
        for (int i = 0; i < 4; i++) {
            av[i] = *reinterpret_cast<const float4*>(aptr[i]);
            bv[i] = *reinterpret_cast<const float4*>(bptr[i]);
        }
        store_stage(smem);
        __syncthreads();
    }

    for (int c = 0; c < KCH; c++) {
        // prefetch chunk c+1 into registers
        if (c + 1 < KCH) {
            const int k0 = (c + 1) * 32;
#pragma unroll
            for (int i = 0; i < 4; i++) {
                if (k0 + c4L[i] * 4 < NIN) {
                    av[i] = *reinterpret_cast<const float4*>(aptr[i] + k0);
                    bv[i] = *reinterpret_cast<const float4*>(bptr[i] + k0);
                } else {
                    av[i] = make_float4(0.f, 0.f, 0.f, 0.f);
                    bv[i] = make_float4(0.f, 0.f, 0.f, 0.f);
                }
            }
        }

        // compute on stage c&1; four 16-row quarters with chunk-local accT
        const uint32_t stg = sbase + (uint32_t)(c & 1) * STAGE_SB;
#pragma unroll
        for (int mh = 0; mh < 4; mh++) {
            float accT[2][4][4];      // [group: hh / c][nj][q]
#pragma unroll
            for (int g = 0; g < 2; g++)
#pragma unroll
                for (int nj = 0; nj < 4; nj++)
#pragma unroll
                    for (int q = 0; q < 4; q++) accT[g][nj][q] = 0.f;

#pragma unroll
            for (int ks = 0; ks < 2; ks++) {
                uint32_t ah[4], al[4], bh[4][2], bl[4][2];
                const uint32_t ao = stg +
                    (uint32_t)((a_r + mh * 16) * ROWB + (ks * 16 + a_c) * 2);
                ldm_x4(ao + OFF_AHI, ah[0], ah[1], ah[2], ah[3]);
                ldm_x4(ao + OFF_ALO, al[0], al[1], al[2], al[3]);
#pragma unroll
                for (int nt = 0; nt < 2; nt++) {
                    const uint32_t bo = stg +
                        (uint32_t)((b_r + nt * 16) * ROWB + (ks * 16 + b_c) * 2);
                    uint32_t r0, r1, r2, r3;
                    ldm_x4(bo + OFF_BHI, r0, r1, r2, r3);
                    bh[nt * 2][0] = r0; bh[nt * 2][1] = r1;
                    bh[nt * 2 + 1][0] = r2; bh[nt * 2 + 1][1] = r3;
                    ldm_x4(bo + OFF_BLO, r0, r1, r2, r3);
                    bl[nt * 2][0] = r0; bl[nt * 2][1] = r1;
                    bl[nt * 2 + 1][0] = r2; bl[nt * 2 + 1][1] = r3;
                }
#pragma unroll
                for (int nj = 0; nj < 4; nj++) {
                    mma_f16(accT[0][nj], ah, bh[nj]);   // hh
                    mma_f16(accT[1][nj], ah, bl[nj]);   // a_hi * w_lo
                    mma_f16(accT[1][nj], al, bh[nj]);   // a_lo * w_hi
                }
            }

            // RN drain with scale fold: acc += hh + c/2048
#pragma unroll
            for (int nj = 0; nj < 4; nj++)
#pragma unroll
                for (int q = 0; q < 4; q++)
                    acc[mh][nj][q] += accT[0][nj][q]
                                    + accT[1][nj][q] * (1.f / 2048.f);
        }

        // store prefetched chunk into the other stage
        if (c + 1 < KCH) {
            store_stage(smem + ((c + 1) & 1) * STAGE_SB);
            __syncthreads();
        }
    }

    // ---- epilogue: undo W scale (1/1024) ----
    const int mbase = mtile * 128 + MW + (lane >> 2);
    const int nbase = ntile * 128 + NW + (lane & 3) * 2;
    const float S = 1.f / 1024.f;
#pragma unroll
    for (int mi = 0; mi < 4; mi++)
#pragma unroll
        for (int nj = 0; nj < 4; nj++) {
            const int r = mbase + mi * 16;
            const int col = nbase + nj * 8;
            *reinterpret_cast<float2*>(&g_cur[(size_t)r * NHID + col]) =
                make_float2(acc[mi][nj][0] * S, acc[mi][nj][1] * S);
            *reinterpret_cast<float2*>(&g_cur[(size_t)(r + 8) * NHID + col]) =
                make_float2(acc[mi][nj][2] * S, acc[mi][nj][3] * S);
        }
}

// ---------------------------------------------------------------------------
// Kernel 2: per-(b,h) LIF scan; packed spike bits via ballot.
// ---------------------------------------------------------------------------
__global__ __launch_bounds__(256)
void spike_scan_kernel()
{
    const int tid  = blockIdx.x * blockDim.x + threadIdx.x;
    const int BH   = B_ * NHID;
    const int widx = tid >> 5;
    float mem1 = 0.f;

    for (int t = 0; t < T_; t++) {
        const float c = g_cur[(size_t)t * BH + tid];
        const float reset = (mem1 > THR) ? THR : 0.f;
        mem1 = BETA * mem1 + c - reset;
        const unsigned bal = __ballot_sync(0xffffffffu, (mem1 - THR) > 0.f);
        if ((tid & 31) == 0)
            g_spk[(size_t)t * (BH / 32) + widx] = bal;
    }
}

// ---------------------------------------------------------------------------
// Kernel 3: Y[t,b,o] = sum_h spk[t,b,h] * W2[o,h]
// ---------------------------------------------------------------------------
__global__ __launch_bounds__(256)
void ygemm_kernel(const float* __restrict__ W2)
{
    __shared__ float w2s[NOUT * NHID];
    for (int i = threadIdx.x; i < NOUT * NHID; i += blockDim.x)
        w2s[i] = W2[i];
    __syncthreads();

    const int row = blockIdx.x * blockDim.x + threadIdx.x;
    float acc[NOUT];
#pragma unroll
    for (int o = 0; o < NOUT; o++) acc[o] = 0.f;

    const unsigned* sp = g_spk + (size_t)row * (NHID / 32);
#pragma unroll 4
    for (int wd = 0; wd < NHID / 32; wd++) {
        unsigned bits = sp[wd];
        while (bits) {
            const int j = __ffs(bits) - 1;
            bits &= bits - 1;
            const int h = (wd << 5) + j;
#pragma unroll
            for (int o = 0; o < NOUT; o++)
                acc[o] += w2s[o * NHID + h];
        }
    }

    float* yp = g_y + (size_t)row * NOUT;
#pragma unroll
    for (int o = 0; o < NOUT; o++) yp[o] = acc[o];
}

// ---------------------------------------------------------------------------
// Kernel 4: mem2 leaky scan, write output [T, B, NOUT]
// Deep unroll: 16 independent loads in flight per dependency step.
// ---------------------------------------------------------------------------
__global__ __launch_bounds__(256)
void out_scan_kernel(float* __restrict__ out)
{
    const int idx = blockIdx.x * blockDim.x + threadIdx.x;
    if (idx >= B_ * NOUT) return;
    const int BO = B_ * NOUT;
    float mem2 = 0.f;
#pragma unroll
    for (int tb = 0; tb < T_; tb += 16) {
        float v[16];
#pragma unroll
        for (int u = 0; u < 16; u++)
            v[u] = g_y[(size_t)(tb + u) * BO + idx];
#pragma unroll
        for (int u = 0; u < 16; u++) {
            mem2 = BETA * mem2 + v[u];
            out[(size_t)(tb + u) * BO + idx] = mem2;
        }
    }
}

// ---------------------------------------------------------------------------
extern "C" void kernel_launch(void* const* d_in, const int* in_sizes, int n_in,
                              void* d_out, int out_size)
{
    const float* x  = (const float*)d_in[0];   // [B, T, NIN]
    const float* W1 = (const float*)d_in[1];   // [NHID, NIN]
    const float* W2 = (const float*)d_in[2];   // [NOUT, NHID]
    float* out = (float*)d_out;                // [T, B, NOUT]

    cudaFuncSetAttribute(gemm1_mma_kernel,
                         cudaFuncAttributeMaxDynamicSharedMemorySize, SMEM_DYN);

    dim3 grid1(NHID / 128, M_ / 128);          // (8, 256)
    gemm1_mma_kernel<<<grid1, 256, SMEM_DYN>>>(x, W1);

    spike_scan_kernel<<<(B_ * NHID) / 256, 256>>>();

    ygemm_kernel<<<M_ / 256, 256>>>(W2);

    out_scan_kernel<<<(B_ * NOUT + 255) / 256, 256>>>(out);
}